// round 2
// baseline (speedup 1.0000x reference)
#include <cuda_runtime.h>

#define T_DIM 200
#define B_DIM 64
#define E_DIM 64
#define NROWS (T_DIM * B_DIM)   // 12800
#define BH (B_DIM * E_DIM)      // 4096
#define NEG_LOG2E (-1.4426950408889634f)

// ---- scratch (device globals: no allocations allowed) ----
__device__ float g_x1[NROWS * E_DIM];   // pre-scaled by -log2e
__device__ float g_y2[NROWS * E_DIM];
__device__ float g_y3[NROWS * E_DIM];
__device__ float g_q [NROWS * E_DIM];   // pre-scaled by -log2e
__device__ float g_ma[NROWS * E_DIM];
__device__ float g_t0[4 * NROWS * 64];
__device__ float g_t1[4 * NROWS * 32];

__device__ __forceinline__ float ex2f(float x) {
    float r; asm("ex2.approx.f32 %0, %1;" : "=f"(r) : "f"(x)); return r;
}
__device__ __forceinline__ float rcpf(float x) {
    float r; asm("rcp.approx.f32 %0, %1;" : "=f"(r) : "f"(x)); return r;
}
// sigmoid(v) where t = -v*log2e was precomputed:  1/(1+2^t)
__device__ __forceinline__ float sig_sc(float t) {
    return rcpf(1.0f + ex2f(t));
}

// ---- generic batched small GEMM: Y[r,o] = act( sum_k X[r,k]*W[k,o] + b[o] )
struct GemmBatch {
    const float* X[4];
    const float* W[4];
    const float* B[4];
    float*       Y[4];
    int          act[4];   // 0=none, 1=leaky(0.3), 2=scale by -log2e
};

template<int HOUT>
__global__ void __launch_bounds__(256) gemm_k(GemmBatch gb)
{
    constexpr int TC   = HOUT / 4;     // thread-cols
    constexpr int TR   = 256 / TC;     // thread-rows
    constexpr int ROWS = TR * 4;       // rows per block
    __shared__ float Xt[64][ROWS + 4]; // transposed X tile (padded)
    __shared__ float Ws[64][HOUT];
    __shared__ float Bs[HOUT];

    const int tw = blockIdx.y;
    const float* __restrict__ X  = gb.X[tw];
    const float* __restrict__ W  = gb.W[tw];
    const float* __restrict__ Bp = gb.B[tw];
    float* __restrict__ Y        = gb.Y[tw];
    const int act = gb.act[tw];

    const int tid = threadIdx.x;
    const int r0  = blockIdx.x * ROWS;

    for (int idx = tid; idx < 64 * HOUT; idx += 256)
        Ws[idx / HOUT][idx % HOUT] = W[idx];
    if (tid < HOUT) Bs[tid] = Bp ? Bp[tid] : 0.0f;
    for (int idx = tid; idx < ROWS * 64; idx += 256) {
        int r = idx >> 6, k = idx & 63;
        Xt[k][r] = X[(size_t)(r0 + r) * 64 + k];
    }
    __syncthreads();

    const int tc = tid % TC, tr = tid / TC;
    float acc[4][4];
    #pragma unroll
    for (int a = 0; a < 4; a++)
        #pragma unroll
        for (int c = 0; c < 4; c++) acc[a][c] = 0.0f;

    #pragma unroll 8
    for (int k = 0; k < 64; k++) {
        float4 xv = *(const float4*)&Xt[k][tr * 4];
        float4 wv = *(const float4*)&Ws[k][tc * 4];
        float xr[4] = {xv.x, xv.y, xv.z, xv.w};
        float wr[4] = {wv.x, wv.y, wv.z, wv.w};
        #pragma unroll
        for (int a = 0; a < 4; a++)
            #pragma unroll
            for (int c = 0; c < 4; c++) acc[a][c] += xr[a] * wr[c];
    }

    #pragma unroll
    for (int a = 0; a < 4; a++) {
        float4 o;
        float* ov = (float*)&o;
        #pragma unroll
        for (int c = 0; c < 4; c++) {
            float v = acc[a][c] + Bs[tc * 4 + c];
            if (act == 1)      v = (v >= 0.0f) ? v : 0.3f * v;
            else if (act == 2) v = v * NEG_LOG2E;
            ov[c] = v;
        }
        *(float4*)&Y[(size_t)(r0 + tr * 4 + a) * HOUT + tc * 4] = o;
    }
}

// ---- cumsum over time: q = (y2 + cumsum(y3)/(t+1)) * (-log2e)
__global__ void __launch_bounds__(256) cumsum_k()
{
    int bh = blockIdx.x * 256 + threadIdx.x;   // (b,h) in [0,4096)
    float acc = 0.0f;
    for (int t = 0; t < T_DIM; t++) {
        size_t o = (size_t)t * BH + bh;
        acc += g_y3[o];
        float invt = __fdividef(1.0f, (float)(t + 1));
        g_q[o] = (g_y2[o] + acc * invt) * NEG_LOG2E;
    }
}

// ---- dominant kernel: scores + m_a (flash-attention style, lower triangle)
// grid (ceil(T/16), B), 512 threads = 16 warps; warp wid handles i = i0+wid.
__global__ void __launch_bounds__(512) attn_k(const float* __restrict__ inp,
                                              const float* __restrict__ w0)
{
    __shared__ float x1s[32][68];
    __shared__ float ins[32][68];
    __shared__ float qs[16][64];
    __shared__ float w0s[64];

    const int b    = blockIdx.y;
    const int i0   = blockIdx.x * 16;
    const int tid  = threadIdx.x;
    const int wid  = tid >> 5;
    const int lane = tid & 31;
    const int i    = i0 + wid;

    if (tid < 64) w0s[tid] = w0[tid];
    for (int idx = tid; idx < 16 * 64; idx += 512) {
        int r = idx >> 6, h = idx & 63;
        int ii = i0 + r;
        qs[r][h] = (ii < T_DIM) ? g_q[(size_t)ii * BH + b * 64 + h] : 0.0f;
    }
    __syncthreads();

    float macc0 = 0.0f, macc1 = 0.0f;
    const int imax_blk = min(i0 + 15, T_DIM - 1);

    for (int j0 = 0; j0 <= imax_blk; j0 += 32) {
        __syncthreads();
        for (int idx = tid; idx < 32 * 64; idx += 512) {
            int jj = idx >> 6, h = idx & 63;
            int j = j0 + jj;
            float vx = 0.0f, vi = 0.0f;
            if (j < T_DIM) {
                size_t o = (size_t)j * BH + b * 64 + h;
                vx = g_x1[o];
                vi = inp[o];
            }
            x1s[jj][h] = vx;
            ins[jj][h] = vi;
        }
        __syncthreads();

        if (i >= j0 && i < T_DIM) {
            int j = j0 + lane;          // lane <-> j mapping: no shuffle in score
            float s = 0.0f;
            if (j <= i && j < T_DIM) {
                #pragma unroll
                for (int h4 = 0; h4 < 64; h4 += 4) {
                    float4 xv = *(const float4*)&x1s[lane][h4];
                    float4 qv = *(const float4*)&qs[wid][h4];
                    float4 wv = *(const float4*)&w0s[h4];
                    s += wv.x * sig_sc(xv.x + qv.x);
                    s += wv.y * sig_sc(xv.y + qv.y);
                    s += wv.z * sig_sc(xv.z + qv.z);
                    s += wv.w * sig_sc(xv.w + qv.w);
                }
            }
            // rank-1 accumulate: m_a[i,:] += s_j * inputs[j,:], 1 SHFL per j
            #pragma unroll 8
            for (int jj = 0; jj < 32; jj++) {
                float sb = __shfl_sync(0xffffffffu, s, jj);
                macc0 += sb * ins[jj][lane];
                macc1 += sb * ins[jj][lane + 32];
            }
        }
    }

    if (i < T_DIM) {
        size_t o = (size_t)i * BH + b * 64;
        g_ma[o + lane]      = macc0;
        g_ma[o + lane + 32] = macc1;
    }
}

// ---- final: pc = sig(dot32), pv = sig(dot32)*pc
__global__ void __launch_bounds__(256) final_k(float* __restrict__ out)
{
    int r = blockIdx.x * 256 + threadIdx.x;   // exactly 12800 threads
    const float4* pa = (const float4*)(g_t1 + (size_t)0 * NROWS * 32 + (size_t)r * 32);
    const float4* pb = (const float4*)(g_t1 + (size_t)1 * NROWS * 32 + (size_t)r * 32);
    const float4* va = (const float4*)(g_t1 + (size_t)2 * NROWS * 32 + (size_t)r * 32);
    const float4* vb = (const float4*)(g_t1 + (size_t)3 * NROWS * 32 + (size_t)r * 32);
    float zc = 0.0f, zv = 0.0f;
    #pragma unroll
    for (int k = 0; k < 8; k++) {
        float4 a = pa[k], bq = pb[k];
        zc += a.x * bq.x + a.y * bq.y + a.z * bq.z + a.w * bq.w;
        float4 c = va[k], d = vb[k];
        zv += c.x * d.x + c.y * d.y + c.z * d.z + c.w * d.w;
    }
    float pc = sig_sc(zc * NEG_LOG2E);
    float pv = sig_sc(zv * NEG_LOG2E) * pc;
    out[r]         = pc;
    out[NROWS + r] = pv;
}

extern "C" void kernel_launch(void* const* d_in, const int* in_sizes, int n_in,
                              void* d_out, int out_size)
{
    (void)in_sizes; (void)n_in; (void)out_size;
    const float* inp     = (const float*)d_in[0];
    const float* w1k     = (const float*)d_in[1];
    const float* w1b     = (const float*)d_in[2];
    const float* w2k     = (const float*)d_in[3];
    const float* w3k     = (const float*)d_in[4];
    const float* w0k     = (const float*)d_in[5];
    const float* pc_a0_k = (const float*)d_in[6],  *pc_a0_b = (const float*)d_in[7];
    const float* pc_b0_k = (const float*)d_in[8],  *pc_b0_b = (const float*)d_in[9];
    const float* pc_a1_k = (const float*)d_in[10], *pc_a1_b = (const float*)d_in[11];
    const float* pc_b1_k = (const float*)d_in[12], *pc_b1_b = (const float*)d_in[13];
    const float* pv_a0_k = (const float*)d_in[14], *pv_a0_b = (const float*)d_in[15];
    const float* pv_b0_k = (const float*)d_in[16], *pv_b0_b = (const float*)d_in[17];
    const float* pv_a1_k = (const float*)d_in[18], *pv_a1_b = (const float*)d_in[19];
    const float* pv_b1_k = (const float*)d_in[20], *pv_b1_b = (const float*)d_in[21];

    float *x1, *y2, *y3, *ma, *t0, *t1;
    cudaGetSymbolAddress((void**)&x1, g_x1);
    cudaGetSymbolAddress((void**)&y2, g_y2);
    cudaGetSymbolAddress((void**)&y3, g_y3);
    cudaGetSymbolAddress((void**)&ma, g_ma);
    cudaGetSymbolAddress((void**)&t0, g_t0);
    cudaGetSymbolAddress((void**)&t1, g_t1);

    // 1) x1 (scaled), y2, y3
    GemmBatch A = {};
    A.X[0] = inp; A.W[0] = w1k; A.B[0] = w1b;    A.Y[0] = x1; A.act[0] = 2;
    A.X[1] = inp; A.W[1] = w2k; A.B[1] = nullptr; A.Y[1] = y2; A.act[1] = 0;
    A.X[2] = inp; A.W[2] = w3k; A.B[2] = nullptr; A.Y[2] = y3; A.act[2] = 0;
    gemm_k<64><<<dim3(NROWS / 64, 3), 256>>>(A);

    // 2) q = (y2 + cumsum(y3)/(t+1)) * -log2e
    cumsum_k<<<BH / 256, 256>>>();

    // 3) scores + m_a
    attn_k<<<dim3((T_DIM + 15) / 16, B_DIM), 512>>>(inp, w0k);

    // 4) MLP layer 0 (4 towers, 64->64, leaky)
    GemmBatch L0 = {};
    L0.X[0] = ma;  L0.W[0] = pc_a0_k; L0.B[0] = pc_a0_b; L0.Y[0] = t0 + 0 * NROWS * 64; L0.act[0] = 1;
    L0.X[1] = inp; L0.W[1] = pc_b0_k; L0.B[1] = pc_b0_b; L0.Y[1] = t0 + 1 * NROWS * 64; L0.act[1] = 1;
    L0.X[2] = ma;  L0.W[2] = pv_a0_k; L0.B[2] = pv_a0_b; L0.Y[2] = t0 + 2 * NROWS * 64; L0.act[2] = 1;
    L0.X[3] = inp; L0.W[3] = pv_b0_k; L0.B[3] = pv_b0_b; L0.Y[3] = t0 + 3 * NROWS * 64; L0.act[3] = 1;
    gemm_k<64><<<dim3(NROWS / 64, 4), 256>>>(L0);

    // 5) MLP layer 1 (4 towers, 64->32, leaky)
    GemmBatch L1 = {};
    L1.X[0] = t0 + 0 * NROWS * 64; L1.W[0] = pc_a1_k; L1.B[0] = pc_a1_b; L1.Y[0] = t1 + 0 * NROWS * 32; L1.act[0] = 1;
    L1.X[1] = t0 + 1 * NROWS * 64; L1.W[1] = pc_b1_k; L1.B[1] = pc_b1_b; L1.Y[1] = t1 + 1 * NROWS * 32; L1.act[1] = 1;
    L1.X[2] = t0 + 2 * NROWS * 64; L1.W[2] = pv_a1_k; L1.B[2] = pv_a1_b; L1.Y[2] = t1 + 2 * NROWS * 32; L1.act[2] = 1;
    L1.X[3] = t0 + 3 * NROWS * 64; L1.W[3] = pv_b1_k; L1.B[3] = pv_b1_b; L1.Y[3] = t1 + 3 * NROWS * 32; L1.act[3] = 1;
    gemm_k<32><<<dim3(NROWS / 128, 4), 256>>>(L1);

    // 6) pc / pv
    final_k<<<NROWS / 256, 256>>>((float*)d_out);
}

// round 3
// speedup vs baseline: 1.5929x; 1.5929x over previous
#include <cuda_runtime.h>

#define T_DIM 200
#define B_DIM 64
#define E_DIM 64
#define NROWS (T_DIM * B_DIM)   // 12800
#define BH (B_DIM * E_DIM)      // 4096
#define LOG2E 1.4426950408889634f

// ---- scratch (device globals: no allocations allowed) ----
__device__ float g_x1[NROWS * E_DIM];   // pre-scaled by 0.5
__device__ float g_y2[NROWS * E_DIM];
__device__ float g_y3[NROWS * E_DIM];
__device__ float g_q [NROWS * E_DIM];   // pre-scaled by 0.5
__device__ float g_ma[NROWS * E_DIM];
__device__ float g_t0[4 * NROWS * 64];
__device__ float g_part[8 * BH];

__device__ __forceinline__ float ex2f(float x) {
    float r; asm("ex2.approx.f32 %0, %1;" : "=f"(r) : "f"(x)); return r;
}
__device__ __forceinline__ float rcpf(float x) {
    float r; asm("rcp.approx.f32 %0, %1;" : "=f"(r) : "f"(x)); return r;
}
__device__ __forceinline__ float tanhf_a(float x) {
    float r; asm("tanh.approx.f32 %0, %1;" : "=f"(r) : "f"(x)); return r;
}
__device__ __forceinline__ float sigf(float v) {        // full sigmoid
    return rcpf(1.0f + ex2f(-v * LOG2E));
}
__device__ __forceinline__ float leakyf(float v) {
    return (v >= 0.0f) ? v : 0.3f * v;
}

// ============================================================================
// GEMM (HOUT=64): 256 thr, 128-row tile, 8x4 per thread (32 FFMA : 3 LDS.128)
// act: 0=none, 1=leaky, 2=*0.5
// ============================================================================
struct GemmBatch {
    const float* X[4];
    const float* W[4];
    const float* B[4];
    float*       Y[4];
    int          act[4];
};

__global__ void __launch_bounds__(256) gemm64_k(GemmBatch gb)
{
    constexpr int ROWS = 128;
    __shared__ float Xt[64][ROWS + 4];
    __shared__ float Ws[64][64];
    __shared__ float Bs[64];

    const int tw = blockIdx.y;
    const float* __restrict__ X  = gb.X[tw];
    const float* __restrict__ W  = gb.W[tw];
    const float* __restrict__ Bp = gb.B[tw];
    float* __restrict__ Y        = gb.Y[tw];
    const int act = gb.act[tw];

    const int tid = threadIdx.x;
    const int r0  = blockIdx.x * ROWS;

    for (int idx = tid; idx < 64 * 64; idx += 256)
        Ws[idx >> 6][idx & 63] = W[idx];
    if (tid < 64) Bs[tid] = Bp ? Bp[tid] : 0.0f;
    for (int idx = tid; idx < ROWS * 64; idx += 256) {
        int r = idx >> 6, k = idx & 63;
        Xt[k][r] = X[(size_t)(r0 + r) * 64 + k];
    }
    __syncthreads();

    const int tc = tid & 15;        // 16 col-groups * 4 cols
    const int tr = tid >> 4;        // 16 row-groups * 8 rows
    float acc[8][4];
    #pragma unroll
    for (int a = 0; a < 8; a++)
        #pragma unroll
        for (int c = 0; c < 4; c++) acc[a][c] = 0.0f;

    #pragma unroll 8
    for (int k = 0; k < 64; k++) {
        float4 x0 = *(const float4*)&Xt[k][tr * 8];
        float4 x1 = *(const float4*)&Xt[k][tr * 8 + 4];
        float4 wv = *(const float4*)&Ws[k][tc * 4];
        float xr[8] = {x0.x, x0.y, x0.z, x0.w, x1.x, x1.y, x1.z, x1.w};
        float wr[4] = {wv.x, wv.y, wv.z, wv.w};
        #pragma unroll
        for (int a = 0; a < 8; a++)
            #pragma unroll
            for (int c = 0; c < 4; c++) acc[a][c] += xr[a] * wr[c];
    }

    #pragma unroll
    for (int a = 0; a < 8; a++) {
        float4 o; float* ov = (float*)&o;
        #pragma unroll
        for (int c = 0; c < 4; c++) {
            float v = acc[a][c] + Bs[tc * 4 + c];
            if (act == 1)      v = leakyf(v);
            else if (act == 2) v = v * 0.5f;
            ov[c] = v;
        }
        *(float4*)&Y[(size_t)(r0 + tr * 8 + a) * 64 + tc * 4] = o;
    }
}

// ============================================================================
// cumsum 2-phase: q = (y2 + cumsum(y3)/(t+1)) * 0.5
// 8 chunks of 25 timesteps x 4096 columns
// ============================================================================
__global__ void __launch_bounds__(256) scan1_k()
{
    int id = blockIdx.x * 256 + threadIdx.x;   // 32768 threads
    int col = id & (BH - 1);
    int ch  = id >> 12;
    int t0 = ch * 25;
    float s = 0.0f;
    #pragma unroll
    for (int t = 0; t < 25; t++)
        s += g_y3[(size_t)(t0 + t) * BH + col];
    g_part[ch * BH + col] = s;
}

__global__ void __launch_bounds__(256) scan2_k()
{
    int id = blockIdx.x * 256 + threadIdx.x;
    int col = id & (BH - 1);
    int ch  = id >> 12;
    float acc = 0.0f;
    for (int c = 0; c < ch; c++) acc += g_part[c * BH + col];
    int t0 = ch * 25;
    #pragma unroll
    for (int t = 0; t < 25; t++) {
        size_t o = (size_t)(t0 + t) * BH + col;
        acc += g_y3[o];
        float invt = __fdividef(1.0f, (float)(t0 + t + 1));
        g_q[o] = (g_y2[o] + acc * invt) * 0.5f;
    }
}

// ============================================================================
// attention: s[i,j] = 0.5*sum_h w0[h]*tanh(0.5*(x1[j,h]+q[i,h])) + 0.5*sum(w0)
// then m_a[i,:] += s * inputs[j,:].  warp=i, lane=j.
// ============================================================================
__global__ void __launch_bounds__(512) attn_k(const float* __restrict__ inp,
                                              const float* __restrict__ w0)
{
    __shared__ float x1s[32][68];
    __shared__ float ins[32][68];
    __shared__ float qs[16][64];
    __shared__ float w0s[64];

    const int b    = blockIdx.y;
    // heavy/light remap for wave balance (13 i-blocks)
    const int nbx  = gridDim.x;
    const int bx   = blockIdx.x;
    const int ibb  = (bx & 1) ? (nbx - 1 - (bx >> 1)) : (bx >> 1);
    const int i0   = ibb * 16;
    const int tid  = threadIdx.x;
    const int wid  = tid >> 5;
    const int lane = tid & 31;
    const int i    = i0 + wid;

    if (tid < 64) w0s[tid] = w0[tid];
    for (int idx = tid; idx < 16 * 64; idx += 512) {
        int r = idx >> 6, h = idx & 63;
        int ii = i0 + r;
        qs[r][h] = (ii < T_DIM) ? g_q[(size_t)ii * BH + b * 64 + h] : 0.0f;
    }
    __syncthreads();

    float hw0 = 0.0f;                    // 0.5 * sum(w0)
    #pragma unroll 16
    for (int h = 0; h < 64; h++) hw0 += w0s[h];
    hw0 *= 0.5f;

    float macc0 = 0.0f, macc1 = 0.0f;
    const int imax_blk = min(i0 + 15, T_DIM - 1);

    for (int j0 = 0; j0 <= imax_blk; j0 += 32) {
        __syncthreads();
        for (int idx = tid; idx < 32 * 64; idx += 512) {
            int jj = idx >> 6, h = idx & 63;
            int j = j0 + jj;
            float vx = 0.0f, vi = 0.0f;
            if (j < T_DIM) {
                size_t o = (size_t)j * BH + b * 64 + h;
                vx = g_x1[o];
                vi = inp[o];
            }
            x1s[jj][h] = vx;
            ins[jj][h] = vi;
        }
        __syncthreads();

        if (i >= j0 && i < T_DIM) {
            int j = j0 + lane;
            float s = 0.0f;
            if (j <= i && j < T_DIM) {
                float dot = 0.0f;
                #pragma unroll
                for (int h4 = 0; h4 < 64; h4 += 4) {
                    float4 xv = *(const float4*)&x1s[lane][h4];
                    float4 qv = *(const float4*)&qs[wid][h4];
                    float4 wv = *(const float4*)&w0s[h4];
                    dot += wv.x * tanhf_a(xv.x + qv.x);
                    dot += wv.y * tanhf_a(xv.y + qv.y);
                    dot += wv.z * tanhf_a(xv.z + qv.z);
                    dot += wv.w * tanhf_a(xv.w + qv.w);
                }
                s = fmaf(0.5f, dot, hw0);
            }
            #pragma unroll 8
            for (int jj = 0; jj < 32; jj++) {
                float sb = __shfl_sync(0xffffffffu, s, jj);
                macc0 += sb * ins[jj][lane];
                macc1 += sb * ins[jj][lane + 32];
            }
        }
    }

    if (i < T_DIM) {
        size_t o = (size_t)i * BH + b * 64;
        g_ma[o + lane]      = macc0;
        g_ma[o + lane + 32] = macc1;
    }
}

// ============================================================================
// fused L1 + final: all 4 towers (64->32, leaky), product-reduce, sigmoid.
// block: 256 thr = 32 row-groups x 8 col-groups; 128 rows/block, 4r x 4c / thr
// pair p=0: towers 0(a),1(b) -> pc ; pair p=1: towers 2,3 -> pv = sig*pc
// ============================================================================
struct L1FArgs {
    const float* W[4];
    const float* B[4];
};

__global__ void __launch_bounds__(256) l1f_k(L1FArgs la, float* __restrict__ out)
{
    constexpr int ROWS = 128;
    __shared__ float Xa[64][ROWS + 4];
    __shared__ float Xb[64][ROWS + 4];
    __shared__ float Wa[64][32];
    __shared__ float Wb[64][32];
    __shared__ float Ba[32], Bb[32];

    const int tid = threadIdx.x;
    const int r0  = blockIdx.x * ROWS;
    const int tc  = tid & 7;     // 8 col-groups * 4
    const int tr  = tid >> 3;    // 32 row-groups * 4

    float pcv[4];
    float res[2][4];

    #pragma unroll
    for (int p = 0; p < 2; p++) {
        const float* Ta = g_t0 + (size_t)(2 * p)     * NROWS * 64;
        const float* Tb = g_t0 + (size_t)(2 * p + 1) * NROWS * 64;

        __syncthreads();
        for (int idx = tid; idx < ROWS * 64; idx += 256) {
            int r = idx >> 6, k = idx & 63;
            Xa[k][r] = Ta[(size_t)(r0 + r) * 64 + k];
            Xb[k][r] = Tb[(size_t)(r0 + r) * 64 + k];
        }
        for (int idx = tid; idx < 64 * 32; idx += 256) {
            Wa[idx >> 5][idx & 31] = la.W[2 * p][idx];
            Wb[idx >> 5][idx & 31] = la.W[2 * p + 1][idx];
        }
        if (tid < 32) { Ba[tid] = la.B[2 * p][tid]; Bb[tid] = la.B[2 * p + 1][tid]; }
        __syncthreads();

        float aa[4][4], ab[4][4];
        #pragma unroll
        for (int a = 0; a < 4; a++)
            #pragma unroll
            for (int c = 0; c < 4; c++) { aa[a][c] = 0.0f; ab[a][c] = 0.0f; }

        #pragma unroll 8
        for (int k = 0; k < 64; k++) {
            float4 xa = *(const float4*)&Xa[k][tr * 4];
            float4 xb = *(const float4*)&Xb[k][tr * 4];
            float4 wa = *(const float4*)&Wa[k][tc * 4];
            float4 wb = *(const float4*)&Wb[k][tc * 4];
            float xar[4] = {xa.x, xa.y, xa.z, xa.w};
            float xbr[4] = {xb.x, xb.y, xb.z, xb.w};
            float war[4] = {wa.x, wa.y, wa.z, wa.w};
            float wbr[4] = {wb.x, wb.y, wb.z, wb.w};
            #pragma unroll
            for (int a = 0; a < 4; a++)
                #pragma unroll
                for (int c = 0; c < 4; c++) {
                    aa[a][c] += xar[a] * war[c];
                    ab[a][c] += xbr[a] * wbr[c];
                }
        }

        #pragma unroll
        for (int a = 0; a < 4; a++) {
            float z = 0.0f;
            #pragma unroll
            for (int c = 0; c < 4; c++) {
                float va = leakyf(aa[a][c] + Ba[tc * 4 + c]);
                float vb = leakyf(ab[a][c] + Bb[tc * 4 + c]);
                z += va * vb;
            }
            // reduce over 8 col-groups (lanes tr*8 .. tr*8+7 in same warp)
            #pragma unroll
            for (int off = 1; off < 8; off <<= 1)
                z += __shfl_xor_sync(0xffffffffu, z, off);
            res[p][a] = z;
        }
        if (p == 0) {
            #pragma unroll
            for (int a = 0; a < 4; a++) pcv[a] = sigf(res[0][a]);
        }
    }

    if (tc == 0) {
        #pragma unroll
        for (int a = 0; a < 4; a++) {
            int row = r0 + tr * 4 + a;
            float pc = pcv[a];
            float pv = sigf(res[1][a]) * pc;
            out[row]         = pc;
            out[NROWS + row] = pv;
        }
    }
}

// ============================================================================
extern "C" void kernel_launch(void* const* d_in, const int* in_sizes, int n_in,
                              void* d_out, int out_size)
{
    (void)in_sizes; (void)n_in; (void)out_size;
    const float* inp     = (const float*)d_in[0];
    const float* w1k     = (const float*)d_in[1];
    const float* w1b     = (const float*)d_in[2];
    const float* w2k     = (const float*)d_in[3];
    const float* w3k     = (const float*)d_in[4];
    const float* w0k     = (const float*)d_in[5];
    const float* pc_a0_k = (const float*)d_in[6],  *pc_a0_b = (const float*)d_in[7];
    const float* pc_b0_k = (const float*)d_in[8],  *pc_b0_b = (const float*)d_in[9];
    const float* pc_a1_k = (const float*)d_in[10], *pc_a1_b = (const float*)d_in[11];
    const float* pc_b1_k = (const float*)d_in[12], *pc_b1_b = (const float*)d_in[13];
    const float* pv_a0_k = (const float*)d_in[14], *pv_a0_b = (const float*)d_in[15];
    const float* pv_b0_k = (const float*)d_in[16], *pv_b0_b = (const float*)d_in[17];
    const float* pv_a1_k = (const float*)d_in[18], *pv_a1_b = (const float*)d_in[19];
    const float* pv_b1_k = (const float*)d_in[20], *pv_b1_b = (const float*)d_in[21];

    float *x1, *y2, *y3, *ma, *t0;
    cudaGetSymbolAddress((void**)&x1, g_x1);
    cudaGetSymbolAddress((void**)&y2, g_y2);
    cudaGetSymbolAddress((void**)&y3, g_y3);
    cudaGetSymbolAddress((void**)&ma, g_ma);
    cudaGetSymbolAddress((void**)&t0, g_t0);

    // 1) x1 (scaled by 0.5), y2, y3
    GemmBatch A = {};
    A.X[0] = inp; A.W[0] = w1k; A.B[0] = w1b;     A.Y[0] = x1; A.act[0] = 2;
    A.X[1] = inp; A.W[1] = w2k; A.B[1] = nullptr; A.Y[1] = y2; A.act[1] = 0;
    A.X[2] = inp; A.W[2] = w3k; A.B[2] = nullptr; A.Y[2] = y3; A.act[2] = 0;
    gemm64_k<<<dim3(NROWS / 128, 3), 256>>>(A);

    // 2) q = (y2 + cumsum(y3)/(t+1)) * 0.5   (2-phase scan)
    scan1_k<<<(8 * BH) / 256, 256>>>();
    scan2_k<<<(8 * BH) / 256, 256>>>();

    // 3) scores + m_a
    attn_k<<<dim3((T_DIM + 15) / 16, B_DIM), 512>>>(inp, w0k);

    // 4) MLP layer 0 (4 towers, 64->64, leaky)
    GemmBatch L0 = {};
    L0.X[0] = ma;  L0.W[0] = pc_a0_k; L0.B[0] = pc_a0_b; L0.Y[0] = t0 + 0 * (size_t)NROWS * 64; L0.act[0] = 1;
    L0.X[1] = inp; L0.W[1] = pc_b0_k; L0.B[1] = pc_b0_b; L0.Y[1] = t0 + 1 * (size_t)NROWS * 64; L0.act[1] = 1;
    L0.X[2] = ma;  L0.W[2] = pv_a0_k; L0.B[2] = pv_a0_b; L0.Y[2] = t0 + 2 * (size_t)NROWS * 64; L0.act[2] = 1;
    L0.X[3] = inp; L0.W[3] = pv_b0_k; L0.B[3] = pv_b0_b; L0.Y[3] = t0 + 3 * (size_t)NROWS * 64; L0.act[3] = 1;
    gemm64_k<<<dim3(NROWS / 128, 4), 256>>>(L0);

    // 5) fused L1 + product-reduce + sigmoid
    L1FArgs la = {};
    la.W[0] = pc_a1_k; la.B[0] = pc_a1_b;
    la.W[1] = pc_b1_k; la.B[1] = pc_b1_b;
    la.W[2] = pv_a1_k; la.B[2] = pv_a1_b;
    la.W[3] = pv_b1_k; la.B[3] = pv_b1_b;
    l1f_k<<<NROWS / 128, 256>>>(la, (float*)d_out);
}